// round 4
// baseline (speedup 1.0000x reference)
#include <cuda_runtime.h>
#include <cuda_bf16.h>
#include <math.h>

// Problem dims (fixed by the reference)
#define BD 64
#define SD 128
#define ED 1024
#define HD_ 8       // heads
#define DH 128      // head dim
#define KPD 32      // Linformer k
#define MTOT (BD*SD)   // 8192

// Scratch (device globals — allocation-free rule)
__device__ float g_Q [MTOT*ED];
__device__ float g_K [MTOT*ED];
__device__ float g_V [MTOT*ED];
__device__ float g_Kp[BD*HD_*KPD*SD];
__device__ float g_Vp[BD*HD_*KPD*SD];
// bf16 hi/lo pre-split operands
__device__ __nv_bfloat16 g_xh [MTOT*ED];
__device__ __nv_bfloat16 g_xl [MTOT*ED];
__device__ __nv_bfloat16 g_Wh [4*ED*ED];   // q,k,v,o slices
__device__ __nv_bfloat16 g_Wl [4*ED*ED];
__device__ __nv_bfloat16 g_AOh[MTOT*ED];
__device__ __nv_bfloat16 g_AOl[MTOT*ED];

// ---------------------------------------------------------------------------
// helpers
// ---------------------------------------------------------------------------
__device__ __forceinline__ unsigned smem_u32(const void* p) {
    unsigned a;
    asm("{ .reg .u64 t; cvta.to.shared.u64 t, %1; cvt.u32.u64 %0, t; }"
        : "=r"(a) : "l"(p));
    return a;
}
__device__ __forceinline__ void cp16(unsigned dst, const void* src) {
    asm volatile("cp.async.cg.shared.global [%0], [%1], 16;\n"
                 :: "r"(dst), "l"(src));
}
__device__ __forceinline__ void ldsm_x4(unsigned& r0, unsigned& r1,
                                        unsigned& r2, unsigned& r3, unsigned a) {
    asm volatile("ldmatrix.sync.aligned.m8n8.x4.shared.b16 {%0,%1,%2,%3}, [%4];\n"
                 : "=r"(r0), "=r"(r1), "=r"(r2), "=r"(r3) : "r"(a));
}
__device__ __forceinline__ void mma_bf16(
    float& c0, float& c1, float& c2, float& c3,
    unsigned a0, unsigned a1, unsigned a2, unsigned a3,
    unsigned b0, unsigned b1)
{
    asm volatile(
        "mma.sync.aligned.m16n8k16.row.col.f32.bf16.bf16.f32 "
        "{%0,%1,%2,%3}, {%4,%5,%6,%7}, {%8,%9}, {%0,%1,%2,%3};\n"
        : "+f"(c0), "+f"(c1), "+f"(c2), "+f"(c3)
        : "r"(a0), "r"(a1), "r"(a2), "r"(a3), "r"(b0), "r"(b1));
}

// ---------------------------------------------------------------------------
// fp32 -> bf16 hi/lo split (vectorized)
// ---------------------------------------------------------------------------
__global__ void __launch_bounds__(256) split_kernel(
    const float4* __restrict__ in, uint2* __restrict__ hi,
    uint2* __restrict__ lo, int n4)
{
    int i = blockIdx.x * blockDim.x + threadIdx.x;
    if (i >= n4) return;
    float4 v = in[i];
    __nv_bfloat16 hx = __float2bfloat16_rn(v.x);
    __nv_bfloat16 hy = __float2bfloat16_rn(v.y);
    __nv_bfloat16 hz = __float2bfloat16_rn(v.z);
    __nv_bfloat16 hw = __float2bfloat16_rn(v.w);
    __nv_bfloat162 h0(hx, hy), h1(hz, hw);
    __nv_bfloat162 l0(__float2bfloat16_rn(v.x - __bfloat162float(hx)),
                      __float2bfloat16_rn(v.y - __bfloat162float(hy)));
    __nv_bfloat162 l1(__float2bfloat16_rn(v.z - __bfloat162float(hz)),
                      __float2bfloat16_rn(v.w - __bfloat162float(hw)));
    hi[i] = make_uint2(*(unsigned*)&h0, *(unsigned*)&h1);
    lo[i] = make_uint2(*(unsigned*)&l0, *(unsigned*)&l1);
}

// ---------------------------------------------------------------------------
// GEMM: C[M,N] = A * W^T + bias, bf16x3 fp32 emulation, pre-split operands.
// Block 128x128, BK=32, 256 thr = 8 warps (2M x 4N), warp 64x32.
// smem: 4 tiles (Ah,Al,Bh,Bl) of 128 rows x 64B at stride 80B, double buffered.
// ldmatrix fragments, cp.async pipeline.
// ---------------------------------------------------------------------------
#define AROW 80
#define TILE_B (128*AROW)
#define BUF_B (4*TILE_B)     // 40960
#define GSMEM (2*BUF_B)      // 81920

__device__ __forceinline__ void stage_tiles(
    unsigned dbase, int tid,
    const __nv_bfloat16* __restrict__ Ah_p, const __nv_bfloat16* __restrict__ Al_p,
    const __nv_bfloat16* __restrict__ Wh_p, const __nv_bfloat16* __restrict__ Wl_p,
    int k0)
{
#pragma unroll
    for (int u = 0; u < 8; u++) {
        const int arr = u >> 1;
        int c = tid + 256 * (u & 1);     // 0..511
        int row = c >> 2, c16 = c & 3;
        unsigned dst = dbase + arr * TILE_B + row * AROW + c16 * 16;
        const __nv_bfloat16* base =
            (arr == 0) ? Ah_p : (arr == 1) ? Al_p : (arr == 2) ? Wh_p : Wl_p;
        cp16(dst, base + (size_t)row * ED + k0 + c16 * 8);
    }
}

__global__ void __launch_bounds__(256, 2) gemm_tc(
    const __nv_bfloat16* __restrict__ Ah, const __nv_bfloat16* __restrict__ Al,
    const __nv_bfloat16* __restrict__ W0h, const __nv_bfloat16* __restrict__ W0l,
    const float* __restrict__ b0p, float* __restrict__ C0,
    const __nv_bfloat16* __restrict__ W1h, const __nv_bfloat16* __restrict__ W1l,
    const float* __restrict__ b1p, float* __restrict__ C1,
    const __nv_bfloat16* __restrict__ W2h, const __nv_bfloat16* __restrict__ W2l,
    const float* __restrict__ b2p, float* __restrict__ C2)
{
    const __nv_bfloat16* Wh = (blockIdx.z == 0) ? W0h : (blockIdx.z == 1) ? W1h : W2h;
    const __nv_bfloat16* Wl = (blockIdx.z == 0) ? W0l : (blockIdx.z == 1) ? W1l : W2l;
    const float* bias       = (blockIdx.z == 0) ? b0p : (blockIdx.z == 1) ? b1p : b2p;
    float*       C          = (blockIdx.z == 0) ? C0  : (blockIdx.z == 1) ? C1  : C2;

    extern __shared__ char smem[];
    const unsigned sbase = smem_u32(smem);

    const int tid  = threadIdx.x;
    const int lane = tid & 31;
    const int w    = tid >> 5;
    const int wm   = w >> 2;          // 0..1
    const int wn   = w & 3;           // 0..3
    const int gid  = lane >> 2;       // 0..7
    const int tig  = lane & 3;        // 0..3
    const int lr   = lane & 15;
    const int lc   = (lane >> 4) * 16;

    const int bm = blockIdx.y * 128;
    const int bn = blockIdx.x * 128;

    const __nv_bfloat16* Ah_p = Ah + (size_t)bm * ED;
    const __nv_bfloat16* Al_p = Al + (size_t)bm * ED;
    const __nv_bfloat16* Wh_p = Wh + (size_t)bn * ED;
    const __nv_bfloat16* Wl_p = Wl + (size_t)bn * ED;

    float acc[4][4][4];
#pragma unroll
    for (int mt = 0; mt < 4; mt++)
#pragma unroll
        for (int nt = 0; nt < 4; nt++)
#pragma unroll
            for (int i = 0; i < 4; i++) acc[mt][nt][i] = 0.f;

    // prologue: stage k0=0 into buffer 0
    stage_tiles(sbase, tid, Ah_p, Al_p, Wh_p, Wl_p, 0);
    asm volatile("cp.async.commit_group;\n");

    const int NSTAGE = ED / 32;     // 32
    int buf = 0;
    for (int s = 0; s < NSTAGE; s++) {
        if (s + 1 < NSTAGE) {
            stage_tiles(sbase + (buf ^ 1) * BUF_B, tid,
                        Ah_p, Al_p, Wh_p, Wl_p, (s + 1) * 32);
            asm volatile("cp.async.commit_group;\n");
            asm volatile("cp.async.wait_group 1;\n");
        } else {
            asm volatile("cp.async.wait_group 0;\n");
        }
        __syncthreads();

        const unsigned bAh = sbase + buf * BUF_B;
        const unsigned bAl = bAh + TILE_B;
        const unsigned bBh = bAh + 2 * TILE_B;
        const unsigned bBl = bAh + 3 * TILE_B;

#pragma unroll
        for (int kk = 0; kk < 2; kk++) {
            const int kb = kk * 32 + lc;
            unsigned bfh[4][2], bfl[4][2];
#pragma unroll
            for (int np = 0; np < 2; np++) {
                const int n0 = wn * 32 + np * 16;
                unsigned r0, r1, r2, r3;
                ldsm_x4(r0, r1, r2, r3, bBh + (n0 + lr) * AROW + kb);
                bfh[np*2][0] = r0; bfh[np*2+1][0] = r1;
                bfh[np*2][1] = r2; bfh[np*2+1][1] = r3;
                ldsm_x4(r0, r1, r2, r3, bBl + (n0 + lr) * AROW + kb);
                bfl[np*2][0] = r0; bfl[np*2+1][0] = r1;
                bfl[np*2][1] = r2; bfl[np*2+1][1] = r3;
            }
#pragma unroll
            for (int mt = 0; mt < 4; mt++) {
                const int m0 = wm * 64 + mt * 16;
                unsigned aH[4], aL[4];
                ldsm_x4(aH[0], aH[1], aH[2], aH[3], bAh + (m0 + lr) * AROW + kb);
                ldsm_x4(aL[0], aL[1], aL[2], aL[3], bAl + (m0 + lr) * AROW + kb);
#pragma unroll
                for (int nt = 0; nt < 4; nt++) {
                    mma_bf16(acc[mt][nt][0], acc[mt][nt][1],
                             acc[mt][nt][2], acc[mt][nt][3],
                             aH[0], aH[1], aH[2], aH[3],
                             bfh[nt][0], bfh[nt][1]);
                    mma_bf16(acc[mt][nt][0], acc[mt][nt][1],
                             acc[mt][nt][2], acc[mt][nt][3],
                             aH[0], aH[1], aH[2], aH[3],
                             bfl[nt][0], bfl[nt][1]);
                    mma_bf16(acc[mt][nt][0], acc[mt][nt][1],
                             acc[mt][nt][2], acc[mt][nt][3],
                             aL[0], aL[1], aL[2], aL[3],
                             bfh[nt][0], bfh[nt][1]);
                }
            }
        }
        __syncthreads();
        buf ^= 1;
    }

    // Epilogue: bias add + store
#pragma unroll
    for (int nt = 0; nt < 4; nt++) {
        int col = bn + wn * 32 + nt * 8 + tig * 2;
        float bb0 = __ldg(bias + col);
        float bb1 = __ldg(bias + col + 1);
#pragma unroll
        for (int mt = 0; mt < 4; mt++) {
            int row = bm + wm * 64 + mt * 16 + gid;
            float2 v0 = make_float2(acc[mt][nt][0] + bb0, acc[mt][nt][1] + bb1);
            float2 v1 = make_float2(acc[mt][nt][2] + bb0, acc[mt][nt][3] + bb1);
            *(float2*)(C + (size_t)row * ED + col)       = v0;
            *(float2*)(C + (size_t)(row + 8) * ED + col) = v1;
        }
    }
}

// ---------------------------------------------------------------------------
// K_proj[b,h,i,s] = sum_d P[d,i] * K[b,s,h*128+d]   (same for V)
// ---------------------------------------------------------------------------
__global__ void __launch_bounds__(256) proj_kernel(
    const float* __restrict__ Kbuf, const float* __restrict__ Vbuf,
    const float* __restrict__ P,
    float* __restrict__ Kp, float* __restrict__ Vp)
{
    const int bh = blockIdx.x;
    const int b = bh >> 3, h = bh & 7;
    __shared__ float Ps[32][32];
    __shared__ float Ks[128][33];
    __shared__ float Vs[128][33];

    const int tid = threadIdx.x;
    float accK[16], accV[16];
#pragma unroll
    for (int r = 0; r < 16; r++) { accK[r] = 0.f; accV[r] = 0.f; }

    const float* kb = Kbuf + ((size_t)b * SD) * ED + h * DH;
    const float* vb = Vbuf + ((size_t)b * SD) * ED + h * DH;

    for (int d0 = 0; d0 < DH; d0 += 32) {
#pragma unroll
        for (int u = 0; u < 4; u++) {
            int e = tid + 256 * u;
            int dd = e >> 5, i = e & 31;
            Ps[dd][i] = P[(size_t)(d0 + dd) * KPD + i];
        }
#pragma unroll
        for (int u = 0; u < 16; u++) {
            int e = tid + 256 * u;
            int s = e >> 5, dd = e & 31;
            Ks[s][dd] = kb[(size_t)s * ED + d0 + dd];
            Vs[s][dd] = vb[(size_t)s * ED + d0 + dd];
        }
        __syncthreads();

#pragma unroll
        for (int r = 0; r < 16; r++) {
            int e = tid + 256 * r;
            int i = e >> 7, s = e & 127;
            float ak = accK[r], av = accV[r];
#pragma unroll
            for (int dd = 0; dd < 32; dd++) {
                float p = Ps[dd][i];
                ak = fmaf(p, Ks[s][dd], ak);
                av = fmaf(p, Vs[s][dd], av);
            }
            accK[r] = ak; accV[r] = av;
        }
        __syncthreads();
    }

    const size_t base = (size_t)bh * (KPD * SD);
#pragma unroll
    for (int r = 0; r < 16; r++) {
        int e = tid + 256 * r;
        Kp[base + e] = accK[r];
        Vp[base + e] = accV[r];
    }
}

// ---------------------------------------------------------------------------
// Per-(b,h) attention; epilogue writes bf16 hi/lo split of AO.
// ---------------------------------------------------------------------------
__global__ void __launch_bounds__(128) attn_kernel(
    const float* __restrict__ Qbuf, const float* __restrict__ Kp,
    const float* __restrict__ Vp,
    __nv_bfloat16* __restrict__ AOh, __nv_bfloat16* __restrict__ AOl)
{
    const int bh = blockIdx.x;
    const int b = bh >> 3, h = bh & 7;
    __shared__ float KpA[128 * 33];
    __shared__ float VpS[32 * 128];
    __shared__ float QS[128][17];

    const int tid = threadIdx.x;
    const size_t base = (size_t)bh * (KPD * SD);

#pragma unroll
    for (int u = 0; u < 32; u++) {
        int e = tid + 128 * u;
        KpA[e] = Kp[base + e];
        VpS[e] = Vp[base + e];
    }
    __syncthreads();

    float sc[32];
#pragma unroll
    for (int j = 0; j < 32; j++) sc[j] = 0.f;

    const float* qb = Qbuf + ((size_t)b * SD) * ED + h * DH;

    for (int d0 = 0; d0 < DH; d0 += 16) {
#pragma unroll
        for (int u = 0; u < 16; u++) {
            int e = tid + 128 * u;
            int s = e >> 4, dd = e & 15;
            QS[s][dd] = qb[(size_t)s * ED + d0 + dd];
        }
        __syncthreads();

        float q[16];
#pragma unroll
        for (int dd = 0; dd < 16; dd++) q[dd] = QS[tid][dd];
#pragma unroll
        for (int j = 0; j < 32; j++) {
            float p = 0.f;
#pragma unroll
            for (int dd = 0; dd < 16; dd++)
                p = fmaf(q[dd], KpA[j * 128 + d0 + dd], p);
            sc[j] += p;
        }
        __syncthreads();
    }

    const float scale = 0.08838834764831845f;  // 1/sqrt(128)
    float m = -1e30f;
#pragma unroll
    for (int j = 0; j < 32; j++) { sc[j] *= scale; m = fmaxf(m, sc[j]); }
    float sum = 0.f;
#pragma unroll
    for (int j = 0; j < 32; j++) { sc[j] = expf(sc[j] - m); sum += sc[j]; }
    float inv = 1.f / sum;

#pragma unroll
    for (int j = 0; j < 32; j++) KpA[tid * 33 + j] = sc[j] * inv;
    __syncthreads();

    __nv_bfloat16* aoh = AOh + ((size_t)b * SD) * ED + h * DH + tid;
    __nv_bfloat16* aol = AOl + ((size_t)b * SD) * ED + h * DH + tid;
    for (int r = 0; r < SD; r++) {
        float acc = 0.f;
#pragma unroll
        for (int j = 0; j < 32; j++)
            acc = fmaf(KpA[r * 33 + j], VpS[j * 128 + tid], acc);
        __nv_bfloat16 hi = __float2bfloat16_rn(acc);
        __nv_bfloat16 lo = __float2bfloat16_rn(acc - __bfloat162float(hi));
        aoh[(size_t)r * ED] = hi;
        aol[(size_t)r * ED] = lo;
    }
}

// ---------------------------------------------------------------------------
extern "C" void kernel_launch(void* const* d_in, const int* in_sizes, int n_in,
                              void* d_out, int out_size)
{
    const float* x  = (const float*)d_in[0];
    const float* Wq = (const float*)d_in[1];
    const float* bq = (const float*)d_in[2];
    const float* Wk = (const float*)d_in[3];
    const float* bk = (const float*)d_in[4];
    const float* Wv = (const float*)d_in[5];
    const float* bv = (const float*)d_in[6];
    const float* P  = (const float*)d_in[7];
    const float* Wo = (const float*)d_in[8];
    const float* bo = (const float*)d_in[9];
    float* out = (float*)d_out;

    float *Qp, *Kbp, *Vbp, *Kpp, *Vpp;
    __nv_bfloat16 *xh, *xl, *wh, *wl, *aoh, *aol;
    cudaGetSymbolAddress((void**)&Qp,  g_Q);
    cudaGetSymbolAddress((void**)&Kbp, g_K);
    cudaGetSymbolAddress((void**)&Vbp, g_V);
    cudaGetSymbolAddress((void**)&Kpp, g_Kp);
    cudaGetSymbolAddress((void**)&Vpp, g_Vp);
    cudaGetSymbolAddress((void**)&xh,  g_xh);
    cudaGetSymbolAddress((void**)&xl,  g_xl);
    cudaGetSymbolAddress((void**)&wh,  g_Wh);
    cudaGetSymbolAddress((void**)&wl,  g_Wl);
    cudaGetSymbolAddress((void**)&aoh, g_AOh);
    cudaGetSymbolAddress((void**)&aol, g_AOl);

    cudaFuncSetAttribute(gemm_tc, cudaFuncAttributeMaxDynamicSharedMemorySize, GSMEM);

    const int WSZ = ED * ED;   // 1M elems per weight

    // splits
    {
        int n4 = (MTOT * ED) / 4;
        split_kernel<<<(n4 + 255) / 256, 256>>>((const float4*)x, (uint2*)xh, (uint2*)xl, n4);
        int w4 = WSZ / 4;
        split_kernel<<<(w4 + 255) / 256, 256>>>((const float4*)Wq, (uint2*)(wh),           (uint2*)(wl),           w4);
        split_kernel<<<(w4 + 255) / 256, 256>>>((const float4*)Wk, (uint2*)(wh + WSZ),     (uint2*)(wl + WSZ),     w4);
        split_kernel<<<(w4 + 255) / 256, 256>>>((const float4*)Wv, (uint2*)(wh + 2*WSZ),   (uint2*)(wl + 2*WSZ),   w4);
        split_kernel<<<(w4 + 255) / 256, 256>>>((const float4*)Wo, (uint2*)(wh + 3*WSZ),   (uint2*)(wl + 3*WSZ),   w4);
    }

    // Fused QKV projection
    dim3 qkv_grid(ED / 128, MTOT / 128, 3);   // (8, 64, 3)
    gemm_tc<<<qkv_grid, 256, GSMEM>>>(xh, xl,
                                      wh,         wl,         bq, Qp,
                                      wh + WSZ,   wl + WSZ,   bk, Kbp,
                                      wh + 2*WSZ, wl + 2*WSZ, bv, Vbp);

    proj_kernel<<<BD * HD_, 256>>>(Kbp, Vbp, P, Kpp, Vpp);
    attn_kernel<<<BD * HD_, 128>>>(Qp, Kpp, Vpp, aoh, aol);

    // Output projection
    dim3 o_grid(ED / 128, MTOT / 128, 1);
    gemm_tc<<<o_grid, 256, GSMEM>>>(aoh, aol,
                                    wh + 3*WSZ, wl + 3*WSZ, bo, out,
                                    wh + 3*WSZ, wl + 3*WSZ, bo, out,
                                    wh + 3*WSZ, wl + 3*WSZ, bo, out);
}

// round 6
// speedup vs baseline: 1.1521x; 1.1521x over previous
#include <cuda_runtime.h>
#include <cuda_bf16.h>
#include <math.h>

// Problem dims (fixed by the reference)
#define BD 64
#define SD 128
#define ED 1024
#define HD_ 8       // heads
#define DH 128      // head dim
#define KPD 32      // Linformer k
#define MTOT (BD*SD)   // 8192
#define NKV 512     // Kp(256) + Vp(256) fused columns

// Scratch (device globals — allocation-free rule)
__device__ float g_Q  [MTOT*ED];
__device__ float g_KV [MTOT*NKV];
__device__ float g_AO [MTOT*ED];
__device__ float g_Wkvp[NKV*ED];
__device__ float g_bkvp[NKV];

// Split x,y into bf16 hi/lo packed pairs
__device__ __forceinline__ void split2(float x, float y, unsigned& hi, unsigned& lo) {
    __nv_bfloat16 hx = __float2bfloat16_rn(x);
    __nv_bfloat16 hy = __float2bfloat16_rn(y);
    __nv_bfloat16 lx = __float2bfloat16_rn(x - __bfloat162float(hx));
    __nv_bfloat16 ly = __float2bfloat16_rn(y - __bfloat162float(hy));
    __nv_bfloat162 h2 = __nv_bfloat162(hx, hy);
    __nv_bfloat162 l2 = __nv_bfloat162(lx, ly);
    hi = *(unsigned*)&h2;
    lo = *(unsigned*)&l2;
}

__device__ __forceinline__ void mma_bf16(
    float& c0, float& c1, float& c2, float& c3,
    unsigned a0, unsigned a1, unsigned a2, unsigned a3,
    unsigned b0, unsigned b1)
{
    asm volatile(
        "mma.sync.aligned.m16n8k16.row.col.f32.bf16.bf16.f32 "
        "{%0,%1,%2,%3}, {%4,%5,%6,%7}, {%8,%9}, {%0,%1,%2,%3};\n"
        : "+f"(c0), "+f"(c1), "+f"(c2), "+f"(c3)
        : "r"(a0), "r"(a1), "r"(a2), "r"(a3), "r"(b0), "r"(b1));
}

// ---------------------------------------------------------------------------
// Fold P into Wk / Wv (and biases):
//  Wkvp[kv*256 + h*32 + i, f] = sum_d P[d,i] * W{k,v}[h*128+d, f]
//  bkvp[kv*256 + h*32 + i]    = sum_d P[d,i] * b{k,v}[h*128+d]
// 16 blocks = (kv, h); 256 threads each.
// ---------------------------------------------------------------------------
__global__ void __launch_bounds__(256) fold_kernel(
    const float* __restrict__ Wk, const float* __restrict__ bk,
    const float* __restrict__ Wv, const float* __restrict__ bv,
    const float* __restrict__ P,
    float* __restrict__ Wkvp, float* __restrict__ bkvp)
{
    const int blk = blockIdx.x;          // 0..15
    const int kv = blk >> 3, h = blk & 7;
    const float* Wsrc = kv ? Wv : Wk;
    const float* bsrc = kv ? bv : bk;

    __shared__ float Ps[128][32];        // P[d][i]
    const int tid = threadIdx.x;
#pragma unroll
    for (int u = 0; u < 16; u++) {
        int e = tid + 256 * u;           // 0..4095
        Ps[e >> 5][e & 31] = P[e];
    }
    __syncthreads();

    if (tid < 32) {
        float s = 0.f;
#pragma unroll 4
        for (int d = 0; d < 128; d++) s = fmaf(Ps[d][tid], bsrc[h * 128 + d], s);
        bkvp[kv * 256 + h * 32 + tid] = s;
    }

    for (int fc = 0; fc < 4; fc++) {
        const int f = fc * 256 + tid;
        float acc[32];
#pragma unroll
        for (int i = 0; i < 32; i++) acc[i] = 0.f;
        for (int d = 0; d < 128; d++) {
            float w = Wsrc[(size_t)(h * 128 + d) * ED + f];
#pragma unroll
            for (int i = 0; i < 32; i++) acc[i] = fmaf(Ps[d][i], w, acc[i]);
        }
#pragma unroll
        for (int i = 0; i < 32; i++)
            Wkvp[(size_t)(kv * 256 + h * 32 + i) * ED + f] = acc[i];
    }
}

// ---------------------------------------------------------------------------
// Tensor-core GEMM with bf16x3 fp32 emulation (proven round-3 kernel + ldc):
// C[M, ldc] = A[M,1024] * W[ldc,1024]^T + bias
// Block tile 128x128, BK=32, 256 threads = 8 warps (2M x 4N), warp 64x32.
// ---------------------------------------------------------------------------
#define SSTR 136

__global__ void __launch_bounds__(256) gemm_tc(
    const float* __restrict__ A, const float* __restrict__ W,
    const float* __restrict__ bias, float* __restrict__ C, int ldc)
{
    __shared__ unsigned AsH[16][SSTR];
    __shared__ unsigned AsL[16][SSTR];
    __shared__ unsigned BsH[16][SSTR];
    __shared__ unsigned BsL[16][SSTR];

    const int tid  = threadIdx.x;
    const int lane = tid & 31;
    const int w    = tid >> 5;
    const int wm   = w >> 2;      // 0..1
    const int wn   = w & 3;       // 0..3
    const int r    = lane >> 2;   // 0..7
    const int cq   = lane & 3;    // 0..3

    const int bm = blockIdx.y * 128;
    const int bn = blockIdx.x * 128;

    const float* Aptr = A + (size_t)bm * ED;
    const float* Wptr = W + (size_t)bn * ED;

    float acc[4][4][4];
#pragma unroll
    for (int mt = 0; mt < 4; mt++)
#pragma unroll
        for (int nt = 0; nt < 4; nt++)
#pragma unroll
            for (int i = 0; i < 4; i++) acc[mt][nt][i] = 0.f;

    for (int k0 = 0; k0 < ED; k0 += 32) {
#pragma unroll
        for (int u = 0; u < 4; u++) {
            int idx = tid + 256 * u;        // 0..1023
            int row = idx >> 3;             // 0..127
            int cg  = idx & 7;              // k offset cg*4 -> pairs cg*2, cg*2+1
            float4 va = *(const float4*)(Aptr + (size_t)row * ED + k0 + cg * 4);
            unsigned h0, l0, h1, l1;
            split2(va.x, va.y, h0, l0);
            split2(va.z, va.w, h1, l1);
            AsH[cg * 2    ][row] = h0; AsL[cg * 2    ][row] = l0;
            AsH[cg * 2 + 1][row] = h1; AsL[cg * 2 + 1][row] = l1;
            float4 vb = *(const float4*)(Wptr + (size_t)row * ED + k0 + cg * 4);
            split2(vb.x, vb.y, h0, l0);
            split2(vb.z, vb.w, h1, l1);
            BsH[cg * 2    ][row] = h0; BsL[cg * 2    ][row] = l0;
            BsH[cg * 2 + 1][row] = h1; BsL[cg * 2 + 1][row] = l1;
        }
        __syncthreads();

#pragma unroll
        for (int kk = 0; kk < 2; kk++) {     // two k16 steps per k0
            const int kb = kk * 8;           // pair-row base
            unsigned afH[4][4], afL[4][4], bfH[4][2], bfL[4][2];
#pragma unroll
            for (int mt = 0; mt < 4; mt++) {
                int m = wm * 64 + mt * 16 + r;
                afH[mt][0] = AsH[kb + cq    ][m    ];
                afH[mt][1] = AsH[kb + cq    ][m + 8];
                afH[mt][2] = AsH[kb + cq + 4][m    ];
                afH[mt][3] = AsH[kb + cq + 4][m + 8];
                afL[mt][0] = AsL[kb + cq    ][m    ];
                afL[mt][1] = AsL[kb + cq    ][m + 8];
                afL[mt][2] = AsL[kb + cq + 4][m    ];
                afL[mt][3] = AsL[kb + cq + 4][m + 8];
            }
#pragma unroll
            for (int nt = 0; nt < 4; nt++) {
                int n = wn * 32 + nt * 8 + r;
                bfH[nt][0] = BsH[kb + cq    ][n];
                bfH[nt][1] = BsH[kb + cq + 4][n];
                bfL[nt][0] = BsL[kb + cq    ][n];
                bfL[nt][1] = BsL[kb + cq + 4][n];
            }
#pragma unroll
            for (int mt = 0; mt < 4; mt++)
#pragma unroll
                for (int nt = 0; nt < 4; nt++) {
                    mma_bf16(acc[mt][nt][0], acc[mt][nt][1],
                             acc[mt][nt][2], acc[mt][nt][3],
                             afH[mt][0], afH[mt][1], afH[mt][2], afH[mt][3],
                             bfH[nt][0], bfH[nt][1]);
                    mma_bf16(acc[mt][nt][0], acc[mt][nt][1],
                             acc[mt][nt][2], acc[mt][nt][3],
                             afH[mt][0], afH[mt][1], afH[mt][2], afH[mt][3],
                             bfL[nt][0], bfL[nt][1]);
                    mma_bf16(acc[mt][nt][0], acc[mt][nt][1],
                             acc[mt][nt][2], acc[mt][nt][3],
                             afL[mt][0], afL[mt][1], afL[mt][2], afL[mt][3],
                             bfH[nt][0], bfH[nt][1]);
                }
        }
        __syncthreads();
    }

    // Epilogue: bias add + store
#pragma unroll
    for (int nt = 0; nt < 4; nt++) {
        int col = bn + wn * 32 + nt * 8 + cq * 2;
        float bb0 = __ldg(bias + col);
        float bb1 = __ldg(bias + col + 1);
#pragma unroll
        for (int mt = 0; mt < 4; mt++) {
            int row = bm + wm * 64 + mt * 16 + r;
            float2 v0 = make_float2(acc[mt][nt][0] + bb0, acc[mt][nt][1] + bb1);
            float2 v1 = make_float2(acc[mt][nt][2] + bb0, acc[mt][nt][3] + bb1);
            *(float2*)(C + (size_t)row * ldc + col)       = v0;
            *(float2*)(C + (size_t)(row + 8) * ldc + col) = v1;
        }
    }
}

// ---------------------------------------------------------------------------
// Per-(b,h) attention from the fused KV_p buffer.
// KVp[(b*128+s)*512 + h*32 + j]        -> K_proj[b,h,j,s]
// KVp[(b*128+s)*512 + 256 + h*32 + j]  -> V_proj[b,h,j,s]
// scores[s,j] = sum_t Q[b,s,h*128+t] * K_proj[j,t]; softmax over j (32);
// out[s,t'] = sum_j attn[s,j] * V_proj[j,t'] -> AO[b,s,h*128+t']
// ---------------------------------------------------------------------------
__global__ void __launch_bounds__(128) attn_kernel(
    const float* __restrict__ Qbuf, const float* __restrict__ KVp,
    float* __restrict__ AO)
{
    const int bh = blockIdx.x;
    const int b = bh >> 3, h = bh & 7;
    __shared__ float Kps[32 * 129];   // [j][t] padded; later reused as attn[j][s]
    __shared__ float Vps[32 * 129];   // [j][t'] padded
    __shared__ float QS[128][17];

    const int tid = threadIdx.x;
    const int jj = tid & 31, s4 = tid >> 5;

    // Coalesced stage: lanes load 32 consecutive j for fixed s
    const float* kvb = KVp + ((size_t)b * SD) * NKV + h * 32 + jj;
#pragma unroll
    for (int u = 0; u < 32; u++) {
        int s = s4 + u * 4;
        Kps[jj * 129 + s] = kvb[(size_t)s * NKV];
        Vps[jj * 129 + s] = kvb[(size_t)s * NKV + 256];
    }
    __syncthreads();

    float sc[32];
#pragma unroll
    for (int j = 0; j < 32; j++) sc[j] = 0.f;

    const float* qb = Qbuf + ((size_t)b * SD) * ED + h * DH;

    for (int d0 = 0; d0 < DH; d0 += 16) {
#pragma unroll
        for (int u = 0; u < 16; u++) {
            int e = tid + 128 * u;
            int s = e >> 4, dd = e & 15;
            QS[s][dd] = qb[(size_t)s * ED + d0 + dd];
        }
        __syncthreads();

        float q[16];
#pragma unroll
        for (int dd = 0; dd < 16; dd++) q[dd] = QS[tid][dd];
#pragma unroll
        for (int j = 0; j < 32; j++) {
            float p = 0.f;
#pragma unroll
            for (int dd = 0; dd < 16; dd++)
                p = fmaf(q[dd], Kps[j * 129 + d0 + dd], p);
            sc[j] += p;
        }
        __syncthreads();
    }

    const float scale = 0.08838834764831845f;  // 1/sqrt(128)
    float m = -1e30f;
#pragma unroll
    for (int j = 0; j < 32; j++) { sc[j] *= scale; m = fmaxf(m, sc[j]); }
    float sum = 0.f;
#pragma unroll
    for (int j = 0; j < 32; j++) { sc[j] = expf(sc[j] - m); sum += sc[j]; }
    float inv = 1.f / sum;

    // Reuse Kps as attn[j][s] (Kps fully consumed above)
#pragma unroll
    for (int j = 0; j < 32; j++) Kps[j * 129 + tid] = sc[j] * inv;
    __syncthreads();

    float* ao = AO + ((size_t)b * SD) * ED + h * DH + tid;
    for (int r = 0; r < SD; r++) {
        float acc = 0.f;
#pragma unroll
        for (int j = 0; j < 32; j++)
            acc = fmaf(Kps[j * 129 + r], Vps[j * 129 + tid], acc);
        ao[(size_t)r * ED] = acc;
    }
}

// ---------------------------------------------------------------------------
extern "C" void kernel_launch(void* const* d_in, const int* in_sizes, int n_in,
                              void* d_out, int out_size)
{
    const float* x  = (const float*)d_in[0];
    const float* Wq = (const float*)d_in[1];
    const float* bq = (const float*)d_in[2];
    const float* Wk = (const float*)d_in[3];
    const float* bk = (const float*)d_in[4];
    const float* Wv = (const float*)d_in[5];
    const float* bv = (const float*)d_in[6];
    const float* P  = (const float*)d_in[7];
    const float* Wo = (const float*)d_in[8];
    const float* bo = (const float*)d_in[9];
    float* out = (float*)d_out;

    float *Qp, *KVp, *AOp, *Wkvp, *bkvp;
    cudaGetSymbolAddress((void**)&Qp,   g_Q);
    cudaGetSymbolAddress((void**)&KVp,  g_KV);
    cudaGetSymbolAddress((void**)&AOp,  g_AO);
    cudaGetSymbolAddress((void**)&Wkvp, g_Wkvp);
    cudaGetSymbolAddress((void**)&bkvp, g_bkvp);

    // Fold P into K/V weights+biases (tiny)
    fold_kernel<<<16, 256>>>(Wk, bk, Wv, bv, P, Wkvp, bkvp);

    // Q projection: [8192,1024] x [1024,1024]^T
    gemm_tc<<<dim3(ED / 128, MTOT / 128), 256>>>(x, Wq, bq, Qp, ED);

    // Fused K_proj/V_proj: [8192,1024] x [512,1024]^T
    gemm_tc<<<dim3(NKV / 128, MTOT / 128), 256>>>(x, Wkvp, bkvp, KVp, NKV);

    // Attention
    attn_kernel<<<BD * HD_, 128>>>(Qp, KVp, AOp);

    // Output projection
    gemm_tc<<<dim3(ED / 128, MTOT / 128), 256>>>(AOp, Wo, bo, out, ED);
}

// round 7
// speedup vs baseline: 1.3943x; 1.2102x over previous
#include <cuda_runtime.h>
#include <cuda_bf16.h>
#include <math.h>

// Problem dims (fixed by the reference)
#define BD 64
#define SD 128
#define ED 1024
#define HD_ 8       // heads
#define DH 128      // head dim
#define KPD 32      // Linformer k
#define MTOT (BD*SD)   // 8192
#define NKV 512     // Kp(256) + Vp(256) fused columns

// Scratch (device globals — allocation-free rule)
__device__ float g_KV  [MTOT*NKV];        // x @ Wkvp^T
__device__ float g_Wkvp[NKV*ED];
__device__ float g_bkvp[NKV];
__device__ float g_WqT [ED*ED];           // [h][e][t] = Wq[h*128+t, e]
__device__ float g_Kpt [16384*128];       // [h][b][j][t]
__device__ float g_Vpt [16384*128];       // [h][b][j][t]
__device__ float g_c   [BD*256];          // [b][h*32+j]
__device__ float g_G   [16384*1024];      // [h][(b,j)][e]
__device__ float g_ZT  [8*1024*2048];     // [h][n][(b,j)]
__device__ float g_attn[MTOT*256];        // [b*128+s][h*32+j]

// ---------------------------------------------------------------------------
// helpers: bf16 hi/lo split + bf16 MMA
// ---------------------------------------------------------------------------
__device__ __forceinline__ void split2(float x, float y, unsigned& hi, unsigned& lo) {
    __nv_bfloat16 hx = __float2bfloat16_rn(x);
    __nv_bfloat16 hy = __float2bfloat16_rn(y);
    __nv_bfloat16 lx = __float2bfloat16_rn(x - __bfloat162float(hx));
    __nv_bfloat16 ly = __float2bfloat16_rn(y - __bfloat162float(hy));
    __nv_bfloat162 h2 = __nv_bfloat162(hx, hy);
    __nv_bfloat162 l2 = __nv_bfloat162(lx, ly);
    hi = *(unsigned*)&h2;
    lo = *(unsigned*)&l2;
}
__device__ __forceinline__ void mma_bf16(
    float& c0, float& c1, float& c2, float& c3,
    unsigned a0, unsigned a1, unsigned a2, unsigned a3,
    unsigned b0, unsigned b1)
{
    asm volatile(
        "mma.sync.aligned.m16n8k16.row.col.f32.bf16.bf16.f32 "
        "{%0,%1,%2,%3}, {%4,%5,%6,%7}, {%8,%9}, {%0,%1,%2,%3};\n"
        : "+f"(c0), "+f"(c1), "+f"(c2), "+f"(c3)
        : "r"(a0), "r"(a1), "r"(a2), "r"(a3), "r"(b0), "r"(b1));
}

#define SSTR 136

// Shared MMA macro body pieces are written per-kernel (no templates) for clarity.

// ---------------------------------------------------------------------------
// Fold P into Wk / Wv (and biases)
// ---------------------------------------------------------------------------
__global__ void __launch_bounds__(256) fold_kernel(
    const float* __restrict__ Wk, const float* __restrict__ bk,
    const float* __restrict__ Wv, const float* __restrict__ bv,
    const float* __restrict__ P,
    float* __restrict__ Wkvp, float* __restrict__ bkvp)
{
    const int blk = blockIdx.x;          // 0..15
    const int kv = blk >> 3, h = blk & 7;
    const float* Wsrc = kv ? Wv : Wk;
    const float* bsrc = kv ? bv : bk;

    __shared__ float Ps[128][32];
    const int tid = threadIdx.x;
#pragma unroll
    for (int u = 0; u < 16; u++) {
        int e = tid + 256 * u;
        Ps[e >> 5][e & 31] = P[e];
    }
    __syncthreads();

    if (tid < 32) {
        float s = 0.f;
#pragma unroll 4
        for (int d = 0; d < 128; d++) s = fmaf(Ps[d][tid], bsrc[h * 128 + d], s);
        bkvp[kv * 256 + h * 32 + tid] = s;
    }

    for (int fc = 0; fc < 4; fc++) {
        const int f = fc * 256 + tid;
        float acc[32];
#pragma unroll
        for (int i = 0; i < 32; i++) acc[i] = 0.f;
        for (int d = 0; d < 128; d++) {
            float w = Wsrc[(size_t)(h * 128 + d) * ED + f];
#pragma unroll
            for (int i = 0; i < 32; i++) acc[i] = fmaf(Ps[d][i], w, acc[i]);
        }
#pragma unroll
        for (int i = 0; i < 32; i++)
            Wkvp[(size_t)(kv * 256 + h * 32 + i) * ED + f] = acc[i];
    }
}

// ---------------------------------------------------------------------------
// Wq transpose: WqT[(h*1024+e)*128 + t] = Wq[(h*128+t)*1024 + e]
// ---------------------------------------------------------------------------
__global__ void __launch_bounds__(256) wq_trans(
    const float* __restrict__ Wq, float* __restrict__ WqT)
{
    __shared__ float tile[32][33];
    const int h  = blockIdx.z;
    const int e0 = blockIdx.x * 32;
    const int t0 = blockIdx.y * 32;
    const int tx = threadIdx.x & 31;
    const int ty = threadIdx.x >> 5;    // 0..7
#pragma unroll
    for (int r = 0; r < 4; r++) {
        int tl = ty + r * 8;
        tile[tl][tx] = Wq[(size_t)(h * 128 + t0 + tl) * ED + e0 + tx];
    }
    __syncthreads();
#pragma unroll
    for (int r = 0; r < 4; r++) {
        int el = ty + r * 8;
        WqT[(size_t)(h * 1024 + e0 + el) * 128 + t0 + tx] = tile[tx][el];
    }
}

// ---------------------------------------------------------------------------
// KV GEMM: C[8192,512] = x * Wkvp^T + bkvp  (bf16x3, proven round-3 core)
// ---------------------------------------------------------------------------
__global__ void __launch_bounds__(256) gemm_kv(
    const float* __restrict__ A, const float* __restrict__ W,
    const float* __restrict__ bias, float* __restrict__ C)
{
    __shared__ unsigned AsH[16][SSTR];
    __shared__ unsigned AsL[16][SSTR];
    __shared__ unsigned BsH[16][SSTR];
    __shared__ unsigned BsL[16][SSTR];

    const int tid  = threadIdx.x;
    const int lane = tid & 31;
    const int w    = tid >> 5;
    const int wm   = w >> 2, wn = w & 3;
    const int r    = lane >> 2, cq = lane & 3;
    const int bm = blockIdx.y * 128;
    const int bn = blockIdx.x * 128;
    const float* Aptr = A + (size_t)bm * ED;
    const float* Wptr = W + (size_t)bn * ED;

    float acc[4][4][4];
#pragma unroll
    for (int mt = 0; mt < 4; mt++)
#pragma unroll
        for (int nt = 0; nt < 4; nt++)
#pragma unroll
            for (int i = 0; i < 4; i++) acc[mt][nt][i] = 0.f;

    for (int k0 = 0; k0 < ED; k0 += 32) {
#pragma unroll
        for (int u = 0; u < 4; u++) {
            int idx = tid + 256 * u;
            int row = idx >> 3, cg = idx & 7;
            float4 va = *(const float4*)(Aptr + (size_t)row * ED + k0 + cg * 4);
            unsigned h0, l0, h1, l1;
            split2(va.x, va.y, h0, l0); split2(va.z, va.w, h1, l1);
            AsH[cg*2][row] = h0; AsL[cg*2][row] = l0;
            AsH[cg*2+1][row] = h1; AsL[cg*2+1][row] = l1;
            float4 vb = *(const float4*)(Wptr + (size_t)row * ED + k0 + cg * 4);
            split2(vb.x, vb.y, h0, l0); split2(vb.z, vb.w, h1, l1);
            BsH[cg*2][row] = h0; BsL[cg*2][row] = l0;
            BsH[cg*2+1][row] = h1; BsL[cg*2+1][row] = l1;
        }
        __syncthreads();
#pragma unroll
        for (int kk = 0; kk < 2; kk++) {
            const int kb = kk * 8;
            unsigned afH[4][4], afL[4][4], bfH[4][2], bfL[4][2];
#pragma unroll
            for (int mt = 0; mt < 4; mt++) {
                int m = wm * 64 + mt * 16 + r;
                afH[mt][0]=AsH[kb+cq][m];   afH[mt][1]=AsH[kb+cq][m+8];
                afH[mt][2]=AsH[kb+cq+4][m]; afH[mt][3]=AsH[kb+cq+4][m+8];
                afL[mt][0]=AsL[kb+cq][m];   afL[mt][1]=AsL[kb+cq][m+8];
                afL[mt][2]=AsL[kb+cq+4][m]; afL[mt][3]=AsL[kb+cq+4][m+8];
            }
#pragma unroll
            for (int nt = 0; nt < 4; nt++) {
                int n = wn * 32 + nt * 8 + r;
                bfH[nt][0]=BsH[kb+cq][n]; bfH[nt][1]=BsH[kb+cq+4][n];
                bfL[nt][0]=BsL[kb+cq][n]; bfL[nt][1]=BsL[kb+cq+4][n];
            }
#pragma unroll
            for (int mt = 0; mt < 4; mt++)
#pragma unroll
                for (int nt = 0; nt < 4; nt++) {
                    mma_bf16(acc[mt][nt][0],acc[mt][nt][1],acc[mt][nt][2],acc[mt][nt][3],
                             afH[mt][0],afH[mt][1],afH[mt][2],afH[mt][3],bfH[nt][0],bfH[nt][1]);
                    mma_bf16(acc[mt][nt][0],acc[mt][nt][1],acc[mt][nt][2],acc[mt][nt][3],
                             afH[mt][0],afH[mt][1],afH[mt][2],afH[mt][3],bfL[nt][0],bfL[nt][1]);
                    mma_bf16(acc[mt][nt][0],acc[mt][nt][1],acc[mt][nt][2],acc[mt][nt][3],
                             afL[mt][0],afL[mt][1],afL[mt][2],afL[mt][3],bfH[nt][0],bfH[nt][1]);
                }
        }
        __syncthreads();
    }
#pragma unroll
    for (int nt = 0; nt < 4; nt++) {
        int col = bn + wn * 32 + nt * 8 + cq * 2;
        float bb0 = __ldg(bias + col), bb1 = __ldg(bias + col + 1);
#pragma unroll
        for (int mt = 0; mt < 4; mt++) {
            int row = bm + wm * 64 + mt * 16 + r;
            float2 v0 = make_float2(acc[mt][nt][0]+bb0, acc[mt][nt][1]+bb1);
            float2 v1 = make_float2(acc[mt][nt][2]+bb0, acc[mt][nt][3]+bb1);
            *(float2*)(C + (size_t)row * NKV + col)       = v0;
            *(float2*)(C + (size_t)(row + 8) * NKV + col) = v1;
        }
    }
}

// ---------------------------------------------------------------------------
// Transpose KVp -> Kpt/Vpt [h][b][j][t]
// ---------------------------------------------------------------------------
__global__ void __launch_bounds__(256) trans_kv(
    const float* __restrict__ KVp, float* __restrict__ Kpt, float* __restrict__ Vpt)
{
    __shared__ float tile[32][129];
    const int cc = blockIdx.x;    // 0..15 (32-col chunk)
    const int b  = blockIdx.y;
    const int tid = threadIdx.x;
#pragma unroll
    for (int u = 0; u < 16; u++) {
        int idx = tid + 256 * u;          // 0..4095
        int t = idx >> 5, c = idx & 31;
        tile[c][t] = KVp[((size_t)b * 128 + t) * NKV + cc * 32 + c];
    }
    __syncthreads();
#pragma unroll
    for (int u = 0; u < 16; u++) {
        int idx = tid + 256 * u;
        int c = idx >> 7, t = idx & 127;
        int col = cc * 32 + c;
        float v = tile[c][t];
        if (col < 256) {
            int h = col >> 5, j = col & 31;
            Kpt[((size_t)(h * 64 + b) * 32 + j) * 128 + t] = v;
        } else {
            int c2 = col - 256;
            int h = c2 >> 5, j = c2 & 31;
            Vpt[((size_t)(h * 64 + b) * 32 + j) * 128 + t] = v;
        }
    }
}

// ---------------------------------------------------------------------------
// c[b][h*32+j] = sum_t Kpt[h,b,j,t] * bq[h*128+t]
// ---------------------------------------------------------------------------
__global__ void __launch_bounds__(256) c_kernel(
    const float* __restrict__ Kpt, const float* __restrict__ bq,
    float* __restrict__ cvec)
{
    const int b = blockIdx.x, hj = threadIdx.x;
    const int h = hj >> 5, j = hj & 31;
    const float* row = Kpt + ((size_t)(h * 64 + b) * 32 + j) * 128;
    const float* bqh = bq + h * 128;
    float s = 0.f;
#pragma unroll 4
    for (int t = 0; t < 128; t++) s = fmaf(row[t], __ldg(bqh + t), s);
    cvec[b * 256 + hj] = s;
}

// ---------------------------------------------------------------------------
// Batched K=128 GEMM (NT): C[m,n] = sum_t A[m,t]*B[n,t], per-z pointer offsets.
// Used for G (A=Kpt_h, B=WqT_h) and ZT (A=Wo rows w/ lda 1024, B=Vpt_h).
// ---------------------------------------------------------------------------
__global__ void __launch_bounds__(256) gemm_k128(
    const float* __restrict__ A, size_t Az, int lda,
    const float* __restrict__ B, size_t Bz, int ldb,
    float* __restrict__ C, size_t Cz, int ldc)
{
    __shared__ unsigned AsH[16][SSTR];
    __shared__ unsigned AsL[16][SSTR];
    __shared__ unsigned BsH[16][SSTR];
    __shared__ unsigned BsL[16][SSTR];

    const int z = blockIdx.z;
    const float* Ap = A + (size_t)z * Az + (size_t)(blockIdx.y * 128) * lda;
    const float* Bp = B + (size_t)z * Bz + (size_t)(blockIdx.x * 128) * ldb;
    float* Cp = C + (size_t)z * Cz;

    const int tid  = threadIdx.x;
    const int lane = tid & 31;
    const int w    = tid >> 5;
    const int wm   = w >> 2, wn = w & 3;
    const int r    = lane >> 2, cq = lane & 3;

    float acc[4][4][4];
#pragma unroll
    for (int mt = 0; mt < 4; mt++)
#pragma unroll
        for (int nt = 0; nt < 4; nt++)
#pragma unroll
            for (int i = 0; i < 4; i++) acc[mt][nt][i] = 0.f;

    for (int k0 = 0; k0 < 128; k0 += 32) {
#pragma unroll
        for (int u = 0; u < 4; u++) {
            int idx = tid + 256 * u;
            int row = idx >> 3, cg = idx & 7;
            float4 va = *(const float4*)(Ap + (size_t)row * lda + k0 + cg * 4);
            unsigned h0, l0, h1, l1;
            split2(va.x, va.y, h0, l0); split2(va.z, va.w, h1, l1);
            AsH[cg*2][row] = h0; AsL[cg*2][row] = l0;
            AsH[cg*2+1][row] = h1; AsL[cg*2+1][row] = l1;
            float4 vb = *(const float4*)(Bp + (size_t)row * ldb + k0 + cg * 4);
            split2(vb.x, vb.y, h0, l0); split2(vb.z, vb.w, h1, l1);
            BsH[cg*2][row] = h0; BsL[cg*2][row] = l0;
            BsH[cg*2+1][row] = h1; BsL[cg*2+1][row] = l1;
        }
        __syncthreads();
#pragma unroll
        for (int kk = 0; kk < 2; kk++) {
            const int kb = kk * 8;
            unsigned afH[4][4], afL[4][4], bfH[4][2], bfL[4][2];
#pragma unroll
            for (int mt = 0; mt < 4; mt++) {
                int m = wm * 64 + mt * 16 + r;
                afH[mt][0]=AsH[kb+cq][m];   afH[mt][1]=AsH[kb+cq][m+8];
                afH[mt][2]=AsH[kb+cq+4][m]; afH[mt][3]=AsH[kb+cq+4][m+8];
                afL[mt][0]=AsL[kb+cq][m];   afL[mt][1]=AsL[kb+cq][m+8];
                afL[mt][2]=AsL[kb+cq+4][m]; afL[mt][3]=AsL[kb+cq+4][m+8];
            }
#pragma unroll
            for (int nt = 0; nt < 4; nt++) {
                int n = wn * 32 + nt * 8 + r;
                bfH[nt][0]=BsH[kb+cq][n]; bfH[nt][1]=BsH[kb+cq+4][n];
                bfL[nt][0]=BsL[kb+cq][n]; bfL[nt][1]=BsL[kb+cq+4][n];
            }
#pragma unroll
            for (int mt = 0; mt < 4; mt++)
#pragma unroll
                for (int nt = 0; nt < 4; nt++) {
                    mma_bf16(acc[mt][nt][0],acc[mt][nt][1],acc[mt][nt][2],acc[mt][nt][3],
                             afH[mt][0],afH[mt][1],afH[mt][2],afH[mt][3],bfH[nt][0],bfH[nt][1]);
                    mma_bf16(acc[mt][nt][0],acc[mt][nt][1],acc[mt][nt][2],acc[mt][nt][3],
                             afH[mt][0],afH[mt][1],afH[mt][2],afH[mt][3],bfL[nt][0],bfL[nt][1]);
                    mma_bf16(acc[mt][nt][0],acc[mt][nt][1],acc[mt][nt][2],acc[mt][nt][3],
                             afL[mt][0],afL[mt][1],afL[mt][2],afL[mt][3],bfH[nt][0],bfH[nt][1]);
                }
        }
        __syncthreads();
    }
#pragma unroll
    for (int nt = 0; nt < 4; nt++) {
        int col = blockIdx.x * 128 + wn * 32 + nt * 8 + cq * 2;
#pragma unroll
        for (int mt = 0; mt < 4; mt++) {
            int row = blockIdx.y * 128 + wm * 64 + mt * 16 + r;
            float2 v0 = make_float2(acc[mt][nt][0], acc[mt][nt][1]);
            float2 v1 = make_float2(acc[mt][nt][2], acc[mt][nt][3]);
            *(float2*)(Cp + (size_t)row * ldc + col)       = v0;
            *(float2*)(Cp + (size_t)(row + 8) * ldc + col) = v1;
        }
    }
}

// ---------------------------------------------------------------------------
// scores + softmax: per (bn,b): attn[b*128+s][col] where col in [bn*128, +128).
// scores = x_b @ G_rows^T + c, scaled, softmax per (row, h-group of 32).
// Warp wn covers exactly one h-group (32 cols).
// ---------------------------------------------------------------------------
__global__ void __launch_bounds__(256) scores_kernel(
    const float* __restrict__ x, const float* __restrict__ G,
    const float* __restrict__ cvec, float* __restrict__ attn)
{
    __shared__ unsigned AsH[16][SSTR];
    __shared__ unsigned AsL[16][SSTR];
    __shared__ unsigned BsH[16][SSTR];
    __shared__ unsigned BsL[16][SSTR];

    const int bn = blockIdx.x * 128;     // 0 or 128
    const int b  = blockIdx.y;
    const float* Ap = x + (size_t)b * 128 * ED;

    const int tid  = threadIdx.x;
    const int lane = tid & 31;
    const int w    = tid >> 5;
    const int wm   = w >> 2, wn = w & 3;
    const int r    = lane >> 2, cq = lane & 3;

    float acc[4][4][4];
#pragma unroll
    for (int mt = 0; mt < 4; mt++)
#pragma unroll
        for (int nt = 0; nt < 4; nt++)
#pragma unroll
            for (int i = 0; i < 4; i++) acc[mt][nt][i] = 0.f;

    for (int k0 = 0; k0 < ED; k0 += 32) {
#pragma unroll
        for (int u = 0; u < 4; u++) {
            int idx = tid + 256 * u;
            int row = idx >> 3, cg = idx & 7;
            float4 va = *(const float4*)(Ap + (size_t)row * ED + k0 + cg * 4);
            unsigned h0, l0, h1, l1;
            split2(va.x, va.y, h0, l0); split2(va.z, va.w, h1, l1);
            AsH[cg*2][row] = h0; AsL[cg*2][row] = l0;
            AsH[cg*2+1][row] = h1; AsL[cg*2+1][row] = l1;
            // B row remap: ncol -> G[h][(b,j)][:]
            int ncol = bn + row;
            int hh = ncol >> 5, j = ncol & 31;
            const float* src = G + ((size_t)hh * 2048 + b * 32 + j) * 1024 + k0 + cg * 4;
            float4 vb = *(const float4*)src;
            split2(vb.x, vb.y, h0, l0); split2(vb.z, vb.w, h1, l1);
            BsH[cg*2][row] = h0; BsL[cg*2][row] = l0;
            BsH[cg*2+1][row] = h1; BsL[cg*2+1][row] = l1;
        }
        __syncthreads();
#pragma unroll
        for (int kk = 0; kk < 2; kk++) {
            const int kb = kk * 8;
            unsigned afH[4][4], afL[4][4], bfH[4][2], bfL[4][2];
#pragma unroll
            for (int mt = 0; mt < 4; mt++) {
                int m = wm * 64 + mt * 16 + r;
                afH[mt][0]=AsH[kb+cq][m];   afH[mt][1]=AsH[kb+cq][m+8];
                afH[mt][2]=AsH[kb+cq+4][m]; afH[mt][3]=AsH[kb+cq+4][m+8];
                afL[mt][0]=AsL[kb+cq][m];   afL[mt][1]=AsL[kb+cq][m+8];
                afL[mt][2]=AsL[kb+cq+4][m]; afL[mt][3]=AsL[kb+cq+4][m+8];
            }
#pragma unroll
            for (int nt = 0; nt < 4; nt++) {
                int n = wn * 32 + nt * 8 + r;
                bfH[nt][0]=BsH[kb+cq][n]; bfH[nt][1]=BsH[kb+cq+4][n];
                bfL[nt][0]=BsL[kb+cq][n]; bfL[nt][1]=BsL[kb+cq+4][n];
            }
#pragma unroll
            for (int mt = 0; mt < 4; mt++)
#pragma unroll
                for (int nt = 0; nt < 4; nt++) {
                    mma_bf16(acc[mt][nt][0],acc[mt][nt][1],acc[mt][nt][2],acc[mt][nt][3],
                             afH[mt][0],afH[mt][1],afH[mt][2],afH[mt][3],bfH[nt][0],bfH[nt][1]);
                    mma_bf16(acc[mt][nt][0],acc[mt][nt][1],acc[mt][nt][2],acc[mt][nt][3],
                             afH[mt][0],afH[mt][1],afH[mt][2],afH[mt][3],bfL[nt][0],bfL[nt][1]);
                    mma_bf16(acc[mt][nt][0],acc[mt][nt][1],acc[mt][nt][2],acc[mt][nt][3],
                             afL[mt][0],afL[mt][1],afL[mt][2],afL[mt][3],bfH[nt][0],bfH[nt][1]);
                }
        }
        __syncthreads();
    }

    // epilogue: + c, * scale, softmax per row within warp's 32 cols
    const float scale = 0.08838834764831845f;  // 1/sqrt(128)
    float cA[4], cB[4];
#pragma unroll
    for (int nt = 0; nt < 4; nt++) {
        int col = bn + wn * 32 + nt * 8 + cq * 2;
        cA[nt] = __ldg(cvec + b * 256 + col);
        cB[nt] = __ldg(cvec + b * 256 + col + 1);
    }
#pragma unroll
    for (int mt = 0; mt < 4; mt++)
#pragma unroll
        for (int nt = 0; nt < 4; nt++) {
            acc[mt][nt][0] = (acc[mt][nt][0] + cA[nt]) * scale;
            acc[mt][nt][1] = (acc[mt][nt][1] + cB[nt]) * scale;
            acc[mt][nt][2] = (acc[mt][nt][2] + cA[nt]) * scale;
            acc[mt][nt][3] = (acc[mt][nt][3] + cB[nt]) * scale;
        }
#pragma unroll
    for (int mt = 0; mt < 4; mt++) {
        float m0 = -1e30f, m1 = -1e30f;
#pragma unroll
        for (int nt = 0; nt < 4; nt++) {
            m0 = fmaxf(m0, fmaxf(acc[mt][nt][0], acc[mt][nt][1]));
            m1 = fmaxf(m1, fmaxf(acc[mt][nt][2], acc[mt][nt][3]));
        }
        m0 = fmaxf(m0, __shfl_xor_sync(0xffffffffu, m0, 1));
        m0 = fmaxf(m0, __shfl_xor_sync(0xffffffffu, m0, 2));
        m1 = fmaxf(m1, __shfl_xor_sync(0xffffffffu, m1, 1));
        m1 = fmaxf(m1, __shfl_xor_sync(0xffffffffu, m1, 2));
        float s0 = 0.f, s1 = 0.f;
#pragma unroll
        for (int nt = 0; nt < 4; nt++) {
            acc[mt][nt][0] = expf(acc[mt][nt][0] - m0);
            acc[mt][nt][1] = expf(acc[mt][nt][1] - m0);
            acc[mt][nt][2] = expf(acc[mt][nt][2] - m1);
            acc[mt][nt][3] = expf(acc[mt][nt][3] - m1);
            s0 += acc[mt][nt][0] + acc[mt][nt][1];
            s1 += acc[mt][nt][2] + acc[mt][nt][3];
        }
        s0 += __shfl_xor_sync(0xffffffffu, s0, 1);
        s0 += __shfl_xor_sync(0xffffffffu, s0, 2);
        s1 += __shfl_xor_sync(0xffffffffu, s1, 1);
        s1 += __shfl_xor_sync(0xffffffffu, s1, 2);
        float i0 = 1.f / s0, i1 = 1.f / s1;
#pragma unroll
        for (int nt = 0; nt < 4; nt++) {
            acc[mt][nt][0] *= i0; acc[mt][nt][1] *= i0;
            acc[mt][nt][2] *= i1; acc[mt][nt][3] *= i1;
        }
    }
    // write attn [b*128+row][256]
#pragma unroll
    for (int nt = 0; nt < 4; nt++) {
        int col = bn + wn * 32 + nt * 8 + cq * 2;
#pragma unroll
        for (int mt = 0; mt < 4; mt++) {
            int row = wm * 64 + mt * 16 + r;
            *(float2*)(attn + ((size_t)b * 128 + row) * 256 + col) =
                make_float2(acc[mt][nt][0], acc[mt][nt][1]);
            *(float2*)(attn + ((size_t)b * 128 + row + 8) * 256 + col) =
                make_float2(acc[mt][nt][2], acc[mt][nt][3]);
        }
    }
}

// ---------------------------------------------------------------------------
// out GEMM: out[b*128+s][ncol] = sum_{hj} attn[b,s,hj] * ZT[h][ncol][(b,j)] + bo
// K=256, chunk kc == h; B chunk addressing into ZT.
// ---------------------------------------------------------------------------
__global__ void __launch_bounds__(256) out_gemm(
    const float* __restrict__ attn, const float* __restrict__ ZT,
    const float* __restrict__ bias, float* __restrict__ C)
{
    __shared__ unsigned AsH[16][SSTR];
    __shared__ unsigned AsL[16][SSTR];
    __shared__ unsigned BsH[16][SSTR];
    __shared__ unsigned BsL[16][SSTR];

    const int bn = blockIdx.x * 128;
    const int b  = blockIdx.y;
    const float* Ap = attn + (size_t)b * 128 * 256;

    const int tid  = threadIdx.x;
    const int lane = tid & 31;
    const int w    = tid >> 5;
    const int wm   = w >> 2, wn = w & 3;
    const int r    = lane >> 2, cq = lane & 3;

    float acc[4][4][4];
#pragma unroll
    for (int mt = 0; mt < 4; mt++)
#pragma unroll
        for (int nt = 0; nt < 4; nt++)
#pragma unroll
            for (int i = 0; i < 4; i++) acc[mt][nt][i] = 0.f;

    for (int k0 = 0; k0 < 256; k0 += 32) {
        const int kc = k0 >> 5;        // == h
#pragma unroll
        for (int u = 0; u < 4; u++) {
            int idx = tid + 256 * u;
            int row = idx >> 3, cg = idx & 7;
            float4 va = *(const float4*)(Ap + (size_t)row * 256 + k0 + cg * 4);
            unsigned h0, l0, h1, l1;
            split2(va.x, va.y, h0, l0); split2(va.z, va.w, h1, l1);
            AsH[cg*2][row] = h0; AsL[cg*2][row] = l0;
            AsH[cg*2+1][row] = h1; AsL[cg*2+1][row] = l1;
            const float* src = ZT + (size_t)kc * (1024 * 2048)
                                  + (size_t)(bn + row) * 2048 + b * 32 + cg * 4;
            float4 vb = *(const float4*)src;
            split2(vb.x, vb.y, h0, l0); split2(vb.z, vb.w, h1, l1);
            BsH[cg*2][row] = h0; BsL[cg*2][row] = l0;
            BsH[cg*2+1][row] = h1; BsL[cg*2+1][row] = l1;
        }
        __syncthreads();
#pragma unroll
        for (int kk = 0; kk < 2; kk++) {
            const int kb = kk * 8;
            unsigned afH[4][4], afL[4][4], bfH[4][2], bfL[4][2];
#pragma unroll
            for (int mt = 0; mt < 4; mt++) {
                int m = wm * 64 + mt * 16 + r;
                afH[mt][0]=AsH[kb+cq][m];   afH[mt][1]=AsH[kb+cq][m+8];
                afH[mt][2]=AsH[kb+cq+4][m]; afH[mt][3]=AsH[kb+cq+4][m+8];
                afL[mt][0]=AsL[kb+cq][m];   afL[mt][1]=AsL[kb+cq][m+8];
                afL[mt][2]=AsL[kb+cq+4][m]; afL[mt][3]=AsL[kb+cq+4][m+8];
            }
#pragma unroll
            for (int nt = 0; nt < 4; nt++) {
                int n = wn * 32 + nt * 8 + r;
                bfH[nt][0]=BsH[kb+cq][n]; bfH[nt][1]=BsH[kb+cq+4][n];
                bfL[nt][0]=BsL[kb+cq][n]; bfL[nt][1]=BsL[kb+cq+4][n];
            }
#pragma unroll
            for (int mt = 0; mt < 4; mt++)
#pragma unroll
                for (int nt = 0; nt < 4; nt++) {
                    mma_bf16(acc[mt][nt][0],acc[mt][nt][1],acc[mt][nt][2],acc[mt][nt][3],
                             afH[mt][0],afH[mt][1],afH[mt][2],afH[mt][3],bfH[nt][0],bfH[nt][1]);
                    mma_bf16(acc[mt][nt][0],acc[mt][nt][1],acc[mt][nt][2],acc[mt][nt][3],
                             afH[mt][0],afH[mt][1],afH[mt][2],afH[mt][3],bfL[nt][0],bfL[nt][1]);
                    mma_bf16(acc[mt][nt][0],acc[mt][nt][1],acc[mt][nt][2],acc[mt][nt][3],
                             afL[mt][0],afL[mt][1],afL[mt][2],afL[mt][3],bfH[nt][0],bfH[nt][1]);
                }
        }
        __syncthreads();
    }
#pragma unroll
    for (int nt = 0; nt < 4; nt++) {
        int col = bn + wn * 32 + nt * 8 + cq * 2;
        float bb0 = __ldg(bias + col), bb1 = __ldg(bias + col + 1);
#pragma unroll
        for (int mt = 0; mt < 4; mt++) {
            int row = wm * 64 + mt * 16 + r;
            float2 v0 = make_float2(acc[mt][nt][0]+bb0, acc[mt][nt][1]+bb1);
            float2 v1 = make_float2(acc[mt][nt][2]+bb0, acc[mt][nt][3]+bb1);
            *(float2*)(C + ((size_t)b * 128 + row) * ED + col)       = v0;
            *(float2*)(C + ((size_t)b * 128 + row + 8) * ED + col)   = v1;
        }
    }
}

// ---------------------------------------------------------------------------
extern "C" void kernel_launch(void* const* d_in, const int* in_sizes, int n_in,
                              void* d_out, int out_size)
{
    const float* x  = (const float*)d_in[0];
    const float* Wq = (const float*)d_in[1];
    const float* bq = (const float*)d_in[2];
    const float* Wk = (const float*)d_in[3];
    const float* bk = (const float*)d_in[4];
    const float* Wv = (const float*)d_in[5];
    const float* bv = (const float*)d_in[6];
    const float* P  = (const float*)d_in[7];
    const float* Wo = (const float*)d_in[8];
    const float* bo = (const float*)d_in[9];
    float* out = (float*)d_out;

    float *KVp, *Wkvp, *bkvp, *WqT, *Kpt, *Vpt, *cvec, *G, *ZT, *attn;
    cudaGetSymbolAddress((void**)&KVp,  g_KV);
    cudaGetSymbolAddress((void**)&Wkvp, g_Wkvp);
    cudaGetSymbolAddress((void**)&bkvp, g_bkvp);
    cudaGetSymbolAddress((void**)&WqT,  g_WqT);
    cudaGetSymbolAddress((void**)&Kpt,  g_Kpt);
    cudaGetSymbolAddress((void**)&Vpt,  g_Vpt);
    cudaGetSymbolAddress((void**)&cvec, g_c);
    cudaGetSymbolAddress((void**)&G,    g_G);
    cudaGetSymbolAddress((void**)&ZT,   g_ZT);
    cudaGetSymbolAddress((void**)&attn, g_attn);

    // 1. Fold P into K/V weights
    fold_kernel<<<16, 256>>>(Wk, bk, Wv, bv, P, Wkvp, bkvp);
    // 2. Transpose Wq -> WqT[h][e][t]
    wq_trans<<<dim3(32, 4, 8), 256>>>(Wq, WqT);
    // 3. KV projection: [8192,512]
    gemm_kv<<<dim3(NKV / 128, MTOT / 128), 256>>>(x, Wkvp, bkvp, KVp);
    // 4. Transpose KVp -> Kpt/Vpt [h][b][j][t]
    trans_kv<<<dim3(16, BD), 256>>>(KVp, Kpt, Vpt);
    // 5. c vector (bq contribution to scores)
    c_kernel<<<BD, 256>>>(Kpt, bq, cvec);
    // 6. G[h] = Kpt_h @ WqT_h^T   (M=2048, N=1024, K=128)
    gemm_k128<<<dim3(8, 16, 8), 256>>>(Kpt, (size_t)2048 * 128, 128,
                                       WqT, (size_t)1024 * 128, 128,
                                       G,   (size_t)2048 * 1024, 1024);
    // 7. ZT[h] = Wo_h @ Vpt_h^T   (M=1024, N=2048, K=128); A=Wo rows, lda=1024, +h*128
    gemm_k128<<<dim3(16, 8, 8), 256>>>(Wo, (size_t)128, 1024,
                                       Vpt, (size_t)2048 * 128, 128,
                                       ZT,  (size_t)1024 * 2048, 2048);
    // 8. scores + softmax -> attn [8192, 256]
    scores_kernel<<<dim3(2, BD), 256>>>(x, G, cvec, attn);
    // 9. out = attn @ ZT(+bo)
    out_gemm<<<dim3(ED / 128, BD), 256>>>(attn, ZT, bo, out);
}

// round 8
// speedup vs baseline: 1.5358x; 1.1015x over previous
#include <cuda_runtime.h>
#include <cuda_bf16.h>
#include <math.h>

// Problem dims (fixed by the reference)
#define BD 64
#define SD 128
#define ED 1024
#define HD_ 8
#define DH 128
#define KPD 32
#define MTOT (BD*SD)   // 8192
#define NKV 512

// Scratch (device globals — allocation-free rule)
__device__ __nv_bfloat16 g_xh  [MTOT*ED];
__device__ __nv_bfloat16 g_xl  [MTOT*ED];
__device__ __nv_bfloat16 g_Woh [ED*ED];
__device__ __nv_bfloat16 g_Wol [ED*ED];
__device__ __nv_bfloat16 g_Wkvph[NKV*ED];
__device__ __nv_bfloat16 g_Wkvpl[NKV*ED];
__device__ float         g_bkvp[NKV];
__device__ __nv_bfloat16 g_WqTh[ED*ED];
__device__ __nv_bfloat16 g_WqTl[ED*ED];
__device__ float         g_KV  [MTOT*NKV];
__device__ __nv_bfloat16 g_Kpth[16384*128];
__device__ __nv_bfloat16 g_Kptl[16384*128];
__device__ __nv_bfloat16 g_Vpth[16384*128];
__device__ __nv_bfloat16 g_Vptl[16384*128];
__device__ float         g_c   [BD*256];
__device__ __nv_bfloat16 g_Gh  [16384*1024];
__device__ __nv_bfloat16 g_Gl  [16384*1024];
__device__ __nv_bfloat16 g_ZTh [8*1024*2048];
__device__ __nv_bfloat16 g_ZTl [8*1024*2048];
__device__ __nv_bfloat16 g_attnh[MTOT*256];
__device__ __nv_bfloat16 g_attnl[MTOT*256];

// ---------------------------------------------------------------------------
// helpers
// ---------------------------------------------------------------------------
__device__ __forceinline__ unsigned smem_u32(const void* p) {
    unsigned a;
    asm("{ .reg .u64 t; cvta.to.shared.u64 t, %1; cvt.u32.u64 %0, t; }"
        : "=r"(a) : "l"(p));
    return a;
}
__device__ __forceinline__ void cp16(unsigned dst, const void* src) {
    asm volatile("cp.async.cg.shared.global [%0], [%1], 16;\n"
                 :: "r"(dst), "l"(src));
}
__device__ __forceinline__ void ldsm_x4(unsigned& r0, unsigned& r1,
                                        unsigned& r2, unsigned& r3, unsigned a) {
    asm volatile("ldmatrix.sync.aligned.m8n8.x4.shared.b16 {%0,%1,%2,%3}, [%4];\n"
                 : "=r"(r0), "=r"(r1), "=r"(r2), "=r"(r3) : "r"(a));
}
__device__ __forceinline__ void mma_bf16(
    float& c0, float& c1, float& c2, float& c3,
    unsigned a0, unsigned a1, unsigned a2, unsigned a3,
    unsigned b0, unsigned b1)
{
    asm volatile(
        "mma.sync.aligned.m16n8k16.row.col.f32.bf16.bf16.f32 "
        "{%0,%1,%2,%3}, {%4,%5,%6,%7}, {%8,%9}, {%0,%1,%2,%3};\n"
        : "+f"(c0), "+f"(c1), "+f"(c2), "+f"(c3)
        : "r"(a0), "r"(a1), "r"(a2), "r"(a3), "r"(b0), "r"(b1));
}
__device__ __forceinline__ void split1(float x, __nv_bfloat16& h, __nv_bfloat16& l) {
    h = __float2bfloat16_rn(x);
    l = __float2bfloat16_rn(x - __bfloat162float(h));
}

// ---------------------------------------------------------------------------
// fp32 -> bf16 hi/lo split
// ---------------------------------------------------------------------------
__global__ void __launch_bounds__(256) split_kernel(
    const float4* __restrict__ in, uint2* __restrict__ hi,
    uint2* __restrict__ lo, int n4)
{
    int i = blockIdx.x * blockDim.x + threadIdx.x;
    if (i >= n4) return;
    float4 v = in[i];
    __nv_bfloat16 h0,l0,h1,l1,h2,l2,h3,l3;
    split1(v.x,h0,l0); split1(v.y,h1,l1); split1(v.z,h2,l2); split1(v.w,h3,l3);
    __nv_bfloat162 ha(h0,h1), hb(h2,h3), la(l0,l1), lb(l2,l3);
    hi[i] = make_uint2(*(unsigned*)&ha, *(unsigned*)&hb);
    lo[i] = make_uint2(*(unsigned*)&la, *(unsigned*)&lb);
}

// ---------------------------------------------------------------------------
// Fold P into Wk / Wv; outputs bf16 hi/lo weights + fp32 bias
// ---------------------------------------------------------------------------
__global__ void __launch_bounds__(256) fold_kernel(
    const float* __restrict__ Wk, const float* __restrict__ bk,
    const float* __restrict__ Wv, const float* __restrict__ bv,
    const float* __restrict__ P,
    __nv_bfloat16* __restrict__ Wph, __nv_bfloat16* __restrict__ Wpl,
    float* __restrict__ bkvp)
{
    const int blk = blockIdx.x;
    const int kv = blk >> 3, h = blk & 7;
    const float* Wsrc = kv ? Wv : Wk;
    const float* bsrc = kv ? bv : bk;

    __shared__ float Ps[128][32];
    const int tid = threadIdx.x;
#pragma unroll
    for (int u = 0; u < 16; u++) {
        int e = tid + 256 * u;
        Ps[e >> 5][e & 31] = P[e];
    }
    __syncthreads();

    if (tid < 32) {
        float s = 0.f;
#pragma unroll 4
        for (int d = 0; d < 128; d++) s = fmaf(Ps[d][tid], bsrc[h * 128 + d], s);
        bkvp[kv * 256 + h * 32 + tid] = s;
    }

    for (int fc = 0; fc < 4; fc++) {
        const int f = fc * 256 + tid;
        float acc[32];
#pragma unroll
        for (int i = 0; i < 32; i++) acc[i] = 0.f;
        for (int d = 0; d < 128; d++) {
            float w = Wsrc[(size_t)(h * 128 + d) * ED + f];
#pragma unroll
            for (int i = 0; i < 32; i++) acc[i] = fmaf(Ps[d][i], w, acc[i]);
        }
#pragma unroll
        for (int i = 0; i < 32; i++) {
            __nv_bfloat16 hh, ll;
            split1(acc[i], hh, ll);
            size_t idx = (size_t)(kv * 256 + h * 32 + i) * ED + f;
            Wph[idx] = hh; Wpl[idx] = ll;
        }
    }
}

// ---------------------------------------------------------------------------
// Wq transpose -> bf16 hi/lo  WqT[(h*1024+e)*128 + t]
// ---------------------------------------------------------------------------
__global__ void __launch_bounds__(256) wq_trans(
    const float* __restrict__ Wq,
    __nv_bfloat16* __restrict__ Th, __nv_bfloat16* __restrict__ Tl)
{
    __shared__ float tile[32][33];
    const int h  = blockIdx.z;
    const int e0 = blockIdx.x * 32;
    const int t0 = blockIdx.y * 32;
    const int tx = threadIdx.x & 31;
    const int ty = threadIdx.x >> 5;
#pragma unroll
    for (int r = 0; r < 4; r++) {
        int tl = ty + r * 8;
        tile[tl][tx] = Wq[(size_t)(h * 128 + t0 + tl) * ED + e0 + tx];
    }
    __syncthreads();
#pragma unroll
    for (int r = 0; r < 4; r++) {
        int el = ty + r * 8;
        __nv_bfloat16 hh, ll;
        split1(tile[tx][el], hh, ll);
        size_t idx = (size_t)(h * 1024 + e0 + el) * 128 + t0 + tx;
        Th[idx] = hh; Tl[idx] = ll;
    }
}

// ---------------------------------------------------------------------------
// Transpose KVp -> Kpt/Vpt [h][b][j][t], bf16 hi/lo
// ---------------------------------------------------------------------------
__global__ void __launch_bounds__(256) trans_kv(
    const float* __restrict__ KVp,
    __nv_bfloat16* __restrict__ Kh, __nv_bfloat16* __restrict__ Kl,
    __nv_bfloat16* __restrict__ Vh, __nv_bfloat16* __restrict__ Vl)
{
    __shared__ float tile[32][129];
    const int cc = blockIdx.x;
    const int b  = blockIdx.y;
    const int tid = threadIdx.x;
#pragma unroll
    for (int u = 0; u < 16; u++) {
        int idx = tid + 256 * u;
        int t = idx >> 5, c = idx & 31;
        tile[c][t] = KVp[((size_t)b * 128 + t) * NKV + cc * 32 + c];
    }
    __syncthreads();
#pragma unroll
    for (int u = 0; u < 16; u++) {
        int idx = tid + 256 * u;
        int c = idx >> 7, t = idx & 127;
        int col = cc * 32 + c;
        __nv_bfloat16 hh, ll;
        split1(tile[c][t], hh, ll);
        if (col < 256) {
            int h = col >> 5, j = col & 31;
            size_t o = ((size_t)(h * 64 + b) * 32 + j) * 128 + t;
            Kh[o] = hh; Kl[o] = ll;
        } else {
            int c2 = col - 256;
            int h = c2 >> 5, j = c2 & 31;
            size_t o = ((size_t)(h * 64 + b) * 32 + j) * 128 + t;
            Vh[o] = hh; Vl[o] = ll;
        }
    }
}

// ---------------------------------------------------------------------------
// c[b][h*32+j] = sum_t Kpt[h,b,j,t] * bq[h*128+t]   (reads hi+lo)
// ---------------------------------------------------------------------------
__global__ void __launch_bounds__(256) c_kernel(
    const __nv_bfloat16* __restrict__ Kh, const __nv_bfloat16* __restrict__ Kl,
    const float* __restrict__ bq, float* __restrict__ cvec)
{
    const int b = blockIdx.x, hj = threadIdx.x;
    const int h = hj >> 5, j = hj & 31;
    const size_t base = ((size_t)(h * 64 + b) * 32 + j) * 128;
    const float* bqh = bq + h * 128;
    float s = 0.f;
#pragma unroll 4
    for (int t = 0; t < 128; t++)
        s = fmaf(__bfloat162float(Kh[base + t]) + __bfloat162float(Kl[base + t]),
                 __ldg(bqh + t), s);
    cvec[b * 256 + hj] = s;
}

// ---------------------------------------------------------------------------
// Unified pipelined GEMM core (round-4 validated machinery), bf16x3 emulation.
// MODE 0: KVp = x @ Wkvp^T + bkvp            (K=1024, fp32 out, ldc 512)
// MODE 1: G[z] = Kpt_z @ WqT_z^T             (K=128,  bf16 hi/lo out, ldc 1024)
// MODE 2: ZT[z] = Wo(:, z*128:+128) @ Vpt_z^T (K=128, bf16 hi/lo out, ldc 2048)
// MODE 3: attn = softmax((x @ G^T + c)*scale) (K=1024, bf16 hi/lo out, ldc 256)
// MODE 4: out = attn @ ZT + bo               (K=256,  fp32 out, ldc 1024)
// ---------------------------------------------------------------------------
#define AROW 80
#define TILE_B (128*AROW)
#define BUF_B (4*TILE_B)     // 40960
#define GSMEM (2*BUF_B)      // 81920

template<int MODE>
__device__ __forceinline__ void stage_g5(
    unsigned dbase, int tid, int bm, int bn, int z, int bq_, int k0,
    const __nv_bfloat16* __restrict__ Ah, const __nv_bfloat16* __restrict__ Al,
    const __nv_bfloat16* __restrict__ Bh, const __nv_bfloat16* __restrict__ Bl)
{
#pragma unroll
    for (int u = 0; u < 8; u++) {
        const int arr = u >> 1;
        int c = tid + 256 * (u & 1);
        int row = c >> 2, c16 = c & 3;
        unsigned dst = dbase + arr * TILE_B + row * AROW + c16 * 16;
        const __nv_bfloat16* src;
        if (arr < 2) {
            size_t off;
            if (MODE == 0 || MODE == 3)      off = (size_t)(bm + row) * 1024 + k0 + c16 * 8;
            else if (MODE == 1)              off = ((size_t)z * 2048 + bm + row) * 128 + k0 + c16 * 8;
            else if (MODE == 2)              off = (size_t)(bm + row) * 1024 + z * 128 + k0 + c16 * 8;
            else                             off = (size_t)(bm + row) * 256 + k0 + c16 * 8;
            src = (arr == 0 ? Ah : Al) + off;
        } else {
            size_t off;
            if (MODE == 0)                   off = (size_t)(bn + row) * 1024 + k0 + c16 * 8;
            else if (MODE == 1)              off = ((size_t)z * 1024 + bn + row) * 128 + k0 + c16 * 8;
            else if (MODE == 2)              off = ((size_t)z * 2048 + bn + row) * 128 + k0 + c16 * 8;
            else if (MODE == 3) {
                int ncol = bn + row;
                int hh = ncol >> 5, j = ncol & 31;
                off = ((size_t)hh * 2048 + bq_ * 32 + j) * 1024 + k0 + c16 * 8;
            } else {
                int kc = k0 >> 5;
                off = (size_t)kc * (1024 * 2048) + (size_t)(bn + row) * 2048 + bq_ * 32 + c16 * 8;
            }
            src = (arr == 2 ? Bh : Bl) + off;
        }
        cp16(dst, src);
    }
}

template<int MODE>
__global__ void __launch_bounds__(256, 2) g5(
    const __nv_bfloat16* __restrict__ Ah, const __nv_bfloat16* __restrict__ Al,
    const __nv_bfloat16* __restrict__ Bh, const __nv_bfloat16* __restrict__ Bl,
    const float* __restrict__ bias, const float* __restrict__ cvec,
    float* __restrict__ Cf,
    __nv_bfloat16* __restrict__ Ch, __nv_bfloat16* __restrict__ Cl)
{
    constexpr int KTOT = (MODE == 1 || MODE == 2) ? 128 : (MODE == 4 ? 256 : 1024);
    constexpr int NS = KTOT / 32;

    extern __shared__ char smem[];
    const unsigned sbase = smem_u32(smem);

    const int tid  = threadIdx.x;
    const int lane = tid & 31;
    const int w    = tid >> 5;
    const int wm   = w >> 2, wn = w & 3;
    const int gid  = lane >> 2, tig = lane & 3;
    const int lr   = lane & 15;
    const int lc   = (lane >> 4) * 16;

    const int bm = blockIdx.y * 128;
    const int bn = blockIdx.x * 128;
    const int z  = blockIdx.z;
    const int bq_ = blockIdx.y;   // b index for MODE 3/4

    float acc[4][4][4];
#pragma unroll
    for (int mt = 0; mt < 4; mt++)
#pragma unroll
        for (int nt = 0; nt < 4; nt++)
#pragma unroll
            for (int i = 0; i < 4; i++) acc[mt][nt][i] = 0.f;

    stage_g5<MODE>(sbase, tid, bm, bn, z, bq_, 0, Ah, Al, Bh, Bl);
    asm volatile("cp.async.commit_group;\n");

    int buf = 0;
    for (int s = 0; s < NS; s++) {
        if (s + 1 < NS) {
            stage_g5<MODE>(sbase + (buf ^ 1) * BUF_B, tid, bm, bn, z, bq_,
                           (s + 1) * 32, Ah, Al, Bh, Bl);
            asm volatile("cp.async.commit_group;\n");
            asm volatile("cp.async.wait_group 1;\n");
        } else {
            asm volatile("cp.async.wait_group 0;\n");
        }
        __syncthreads();

        const unsigned bAh = sbase + buf * BUF_B;
        const unsigned bAl = bAh + TILE_B;
        const unsigned bBh = bAh + 2 * TILE_B;
        const unsigned bBl = bAh + 3 * TILE_B;

#pragma unroll
        for (int kk = 0; kk < 2; kk++) {
            const int kb = kk * 32 + lc;
            unsigned bfh[4][2], bfl[4][2];
#pragma unroll
            for (int np = 0; np < 2; np++) {
                const int n0 = wn * 32 + np * 16;
                unsigned r0, r1, r2, r3;
                ldsm_x4(r0, r1, r2, r3, bBh + (n0 + lr) * AROW + kb);
                bfh[np*2][0] = r0; bfh[np*2+1][0] = r1;
                bfh[np*2][1] = r2; bfh[np*2+1][1] = r3;
                ldsm_x4(r0, r1, r2, r3, bBl + (n0 + lr) * AROW + kb);
                bfl[np*2][0] = r0; bfl[np*2+1][0] = r1;
                bfl[np*2][1] = r2; bfl[np*2+1][1] = r3;
            }
#pragma unroll
            for (int mt = 0; mt < 4; mt++) {
                const int m0 = wm * 64 + mt * 16;
                unsigned aH[4], aL[4];
                ldsm_x4(aH[0], aH[1], aH[2], aH[3], bAh + (m0 + lr) * AROW + kb);
                ldsm_x4(aL[0], aL[1], aL[2], aL[3], bAl + (m0 + lr) * AROW + kb);
#pragma unroll
                for (int nt = 0; nt < 4; nt++) {
                    mma_bf16(acc[mt][nt][0], acc[mt][nt][1],
                             acc[mt][nt][2], acc[mt][nt][3],
                             aH[0], aH[1], aH[2], aH[3],
                             bfh[nt][0], bfh[nt][1]);
                    mma_bf16(acc[mt][nt][0], acc[mt][nt][1],
                             acc[mt][nt][2], acc[mt][nt][3],
                             aH[0], aH[1], aH[2], aH[3],
                             bfl[nt][0], bfl[nt][1]);
                    mma_bf16(acc[mt][nt][0], acc[mt][nt][1],
                             acc[mt][nt][2], acc[mt][nt][3],
                             aL[0], aL[1], aL[2], aL[3],
                             bfh[nt][0], bfh[nt][1]);
                }
            }
        }
        __syncthreads();
        buf ^= 1;
    }

    // ------------------ epilogues ------------------
    if (MODE == 0 || MODE == 4) {
        const int ldc = (MODE == 0) ? 512 : 1024;
        const int rb  = (MODE == 0) ? bm : bq_ * 128;
#pragma unroll
        for (int nt = 0; nt < 4; nt++) {
            int col = bn + wn * 32 + nt * 8 + tig * 2;
            float bb0 = __ldg(bias + col), bb1 = __ldg(bias + col + 1);
#pragma unroll
            for (int mt = 0; mt < 4; mt++) {
                int row = rb + wm * 64 + mt * 16 + gid;
                *(float2*)(Cf + (size_t)row * ldc + col) =
                    make_float2(acc[mt][nt][0] + bb0, acc[mt][nt][1] + bb1);
                *(float2*)(Cf + (size_t)(row + 8) * ldc + col) =
                    make_float2(acc[mt][nt][2] + bb0, acc[mt][nt][3] + bb1);
            }
        }
    } else if (MODE == 1 || MODE == 2) {
        const int ldc = (MODE == 1) ? 1024 : 2048;
        const int rb  = (MODE == 1) ? z * 2048 + bm : z * 1024 + bm;
#pragma unroll
        for (int nt = 0; nt < 4; nt++) {
            int col = bn + wn * 32 + nt * 8 + tig * 2;
#pragma unroll
            for (int mt = 0; mt < 4; mt++) {
                int row = rb + wm * 64 + mt * 16 + gid;
                __nv_bfloat16 h0, l0, h1, l1;
                split1(acc[mt][nt][0], h0, l0); split1(acc[mt][nt][1], h1, l1);
                *(__nv_bfloat162*)(Ch + (size_t)row * ldc + col) = __nv_bfloat162(h0, h1);
                *(__nv_bfloat162*)(Cl + (size_t)row * ldc + col) = __nv_bfloat162(l0, l1);
                split1(acc[mt][nt][2], h0, l0); split1(acc[mt][nt][3], h1, l1);
                *(__nv_bfloat162*)(Ch + (size_t)(row + 8) * ldc + col) = __nv_bfloat162(h0, h1);
                *(__nv_bfloat162*)(Cl + (size_t)(row + 8) * ldc + col) = __nv_bfloat162(l0, l1);
            }
        }
    } else {   // MODE 3: +c, scale, softmax per (row, 32-col h-group), bf16 hi/lo out
        const float scale = 0.08838834764831845f;
        float cA[4], cB[4];
#pragma unroll
        for (int nt = 0; nt < 4; nt++) {
            int col = bn + wn * 32 + nt * 8 + tig * 2;
            cA[nt] = __ldg(cvec + bq_ * 256 + col);
            cB[nt] = __ldg(cvec + bq_ * 256 + col + 1);
        }
#pragma unroll
        for (int mt = 0; mt < 4; mt++)
#pragma unroll
            for (int nt = 0; nt < 4; nt++) {
                acc[mt][nt][0] = (acc[mt][nt][0] + cA[nt]) * scale;
                acc[mt][nt][1] = (acc[mt][nt][1] + cB[nt]) * scale;
                acc[mt][nt][2] = (acc[mt][nt][2] + cA[nt]) * scale;
                acc[mt][nt][3] = (acc[mt][nt][3] + cB[nt]) * scale;
            }
#pragma unroll
        for (int mt = 0; mt < 4; mt++) {
            float m0 = -1e30f, m1 = -1e30f;
#pragma unroll
            for (int nt = 0; nt < 4; nt++) {
                m0 = fmaxf(m0, fmaxf(acc[mt][nt][0], acc[mt][nt][1]));
                m1 = fmaxf(m1, fmaxf(acc[mt][nt][2], acc[mt][nt][3]));
            }
            m0 = fmaxf(m0, __shfl_xor_sync(0xffffffffu, m0, 1));
            m0 = fmaxf(m0, __shfl_xor_sync(0xffffffffu, m0, 2));
            m1 = fmaxf(m1, __shfl_xor_sync(0xffffffffu, m1, 1));
            m1 = fmaxf(m1, __shfl_xor_sync(0xffffffffu, m1, 2));
            float s0 = 0.f, s1 = 0.f;
#pragma unroll
            for (int nt = 0; nt < 4; nt++) {
                acc[mt][nt][0] = expf(acc[mt][nt][0] - m0);
                acc[mt][nt][1] = expf(acc[mt][nt][1] - m0);
                acc[mt][nt][2] = expf(acc[mt][nt][2] - m1);
                acc[mt][nt][3] = expf(acc[mt][nt][3] - m1);
                s0 += acc[mt][nt][0] + acc[mt][nt][1];
                s1 += acc[mt][nt][2] + acc[mt][nt][3];
            }
            s0 += __shfl_xor_sync(0xffffffffu, s0, 1);
            s0 += __shfl_xor_sync(0xffffffffu, s0, 2);
            s1 += __shfl_xor_sync(0xffffffffu, s1, 1);
            s1 += __shfl_xor_sync(0xffffffffu, s1, 2);
            float i0 = 1.f / s0, i1 = 1.f / s1;
#pragma unroll
            for (int nt = 0; nt < 4; nt++) {
                acc[mt][nt][0] *= i0; acc[mt][nt][1] *= i0;
                acc[mt][nt][2] *= i1; acc[mt][nt][3] *= i1;
            }
        }
#pragma unroll
        for (int nt = 0; nt < 4; nt++) {
            int col = bn + wn * 32 + nt * 8 + tig * 2;
#pragma unroll
            for (int mt = 0; mt < 4; mt++) {
                int row = bq_ * 128 + wm * 64 + mt * 16 + gid;
                __nv_bfloat16 h0, l0, h1, l1;
                split1(acc[mt][nt][0], h0, l0); split1(acc[mt][nt][1], h1, l1);
                *(__nv_bfloat162*)(Ch + (size_t)row * 256 + col) = __nv_bfloat162(h0, h1);
                *(__nv_bfloat162*)(Cl + (size_t)row * 256 + col) = __nv_bfloat162(l0, l1);
                split1(acc[mt][nt][2], h0, l0); split1(acc[mt][nt][3], h1, l1);
                *(__nv_bfloat162*)(Ch + (size_t)(row + 8) * 256 + col) = __nv_bfloat162(h0, h1);
                *(__nv_bfloat162*)(Cl + (size_t)(row + 8) * 256 + col) = __nv_bfloat162(l0, l1);
            }
        }
    }
}

// ---------------------------------------------------------------------------
extern "C" void kernel_launch(void* const* d_in, const int* in_sizes, int n_in,
                              void* d_out, int out_size)
{
    const float* x  = (const float*)d_in[0];
    const float* Wq = (const float*)d_in[1];
    const float* bq = (const float*)d_in[2];
    const float* Wk = (const float*)d_in[3];
    const float* bk = (const float*)d_in[4];
    const float* Wv = (const float*)d_in[5];
    const float* bv = (const float*)d_in[6];
    const float* P  = (const float*)d_in[7];
    const float* Wo = (const float*)d_in[8];
    const float* bo = (const float*)d_in[9];
    float* out = (float*)d_out;

    __nv_bfloat16 *xh,*xl,*Woh,*Wol,*Wkvph,*Wkvpl,*WqTh,*WqTl;
    __nv_bfloat16 *Kpth,*Kptl,*Vpth,*Vptl,*Gh,*Gl,*ZTh,*ZTl,*attnh,*attnl;
    float *bkvp,*KVp,*cvec;
    cudaGetSymbolAddress((void**)&xh, g_xh);     cudaGetSymbolAddress((void**)&xl, g_xl);
    cudaGetSymbolAddress((void**)&Woh, g_Woh);   cudaGetSymbolAddress((void**)&Wol, g_Wol);
    cudaGetSymbolAddress((void**)&Wkvph, g_Wkvph); cudaGetSymbolAddress((void**)&Wkvpl, g_Wkvpl);
    cudaGetSymbolAddress((void**)&bkvp, g_bkvp);
    cudaGetSymbolAddress((void**)&WqTh, g_WqTh); cudaGetSymbolAddress((void**)&WqTl, g_WqTl);
    cudaGetSymbolAddress((void**)&KVp, g_KV);
    cudaGetSymbolAddress((void**)&Kpth, g_Kpth); cudaGetSymbolAddress((void**)&Kptl, g_Kptl);
    cudaGetSymbolAddress((void**)&Vpth, g_Vpth); cudaGetSymbolAddress((void**)&Vptl, g_Vptl);
    cudaGetSymbolAddress((void**)&cvec, g_c);
    cudaGetSymbolAddress((void**)&Gh, g_Gh);     cudaGetSymbolAddress((void**)&Gl, g_Gl);
    cudaGetSymbolAddress((void**)&ZTh, g_ZTh);   cudaGetSymbolAddress((void**)&ZTl, g_ZTl);
    cudaGetSymbolAddress((void**)&attnh, g_attnh); cudaGetSymbolAddress((void**)&attnl, g_attnl);

    cudaFuncSetAttribute(g5<0>, cudaFuncAttributeMaxDynamicSharedMemorySize, GSMEM);
    cudaFuncSetAttribute(g5<1>, cudaFuncAttributeMaxDynamicSharedMemorySize, GSMEM);
    cudaFuncSetAttribute(g5<2>, cudaFuncAttributeMaxDynamicSharedMemorySize, GSMEM);
    cudaFuncSetAttribute(g5<3>, cudaFuncAttributeMaxDynamicSharedMemorySize, GSMEM);
    cudaFuncSetAttribute(g5<4>, cudaFuncAttributeMaxDynamicSharedMemorySize, GSMEM);

    // pre-splits
    split_kernel<<<(MTOT*ED/4 + 255)/256, 256>>>((const float4*)x, (uint2*)xh, (uint2*)xl, MTOT*ED/4);
    split_kernel<<<(ED*ED/4 + 255)/256, 256>>>((const float4*)Wo, (uint2*)Woh, (uint2*)Wol, ED*ED/4);
    fold_kernel<<<16, 256>>>(Wk, bk, Wv, bv, P, Wkvph, Wkvpl, bkvp);
    wq_trans<<<dim3(32, 4, 8), 256>>>(Wq, WqTh, WqTl);

    // KV projection: [8192,512]
    g5<0><<<dim3(NKV/128, MTOT/128), 256, GSMEM>>>(xh, xl, Wkvph, Wkvpl, bkvp, nullptr,
                                                   KVp, nullptr, nullptr);
    trans_kv<<<dim3(16, BD), 256>>>(KVp, Kpth, Kptl, Vpth, Vptl);
    c_kernel<<<BD, 256>>>(Kpth, Kptl, bq, cvec);

    // G[h] = Kpt_h @ WqT_h^T   (M=2048, N=1024, K=128)
    g5<1><<<dim3(8, 16, 8), 256, GSMEM>>>(Kpth, Kptl, WqTh, WqTl, nullptr, nullptr,
                                          nullptr, Gh, Gl);
    // ZT[h] = Wo_h @ Vpt_h^T   (M=1024, N=2048, K=128)
    g5<2><<<dim3(16, 8, 8), 256, GSMEM>>>(Woh, Wol, Vpth, Vptl, nullptr, nullptr,
                                          nullptr, ZTh, ZTl);
    // scores + softmax -> attn hi/lo
    g5<3><<<dim3(2, BD), 256, GSMEM>>>(xh, xl, Gh, Gl, nullptr, cvec,
                                       nullptr, attnh, attnl);
    // out = attn @ ZT + bo
    g5<4><<<dim3(8, BD), 256, GSMEM>>>(attnh, attnl, ZTh, ZTl, bo, nullptr,
                                       out, nullptr, nullptr);
}